// round 9
// baseline (speedup 1.0000x reference)
#include <cuda_runtime.h>
#include <math.h>

#define NC     124
#define CPAD   128
#define CH     64
#define IN_HW  120
#define OUT_HW 480
#define NPIX   (OUT_HW * OUT_HW)   // 230400
#define NTAP   (IN_HW * IN_HW)     // 14400
#define EPSV   1e-8f
#define GRID   148
#define TPB    512
#define STRIDE (GRID * TPB)        // 75776

// ---------------- static device scratch ----------------
__device__ __align__(16) float g_featsT[NTAP * CH];   // (tap, ch)
__device__ int   g_iszero[NC];
__device__ __align__(16) float g_gram[NTAP * 8];      // S,H,V,D,AD per tap
__device__ __align__(16) float g_G[NTAP * CPAD];      // f_t . mn_c
__device__ __align__(16) float g_C[NTAP * CPAD];      // selected coefficient
__device__ float g_acc[NC * CH];
__device__ float g_den[CPAD];
__device__ float g_cnt[CPAD];
__device__ int   g_ctr[8];                             // barrier arrival counters (self-reset)
__device__ int   g_gen;                                // barrier generation (monotonic)

// ---------------- replay-safe grid barrier ----------------
__device__ __forceinline__ void grid_barrier(int p) {
    __syncthreads();
    if (threadIdx.x == 0) {
        volatile int* genp = &g_gen;
        const int g0 = *genp;                // read BEFORE arriving: stable
        __threadfence();
        const int my = atomicAdd(&g_ctr[p], 1);
        if (my == GRID - 1) {
            g_ctr[p] = 0;                    // reset for next replay
            __threadfence();
            atomicAdd(&g_gen, 1);
        } else {
            while (*genp == g0) __nanosleep(64);
        }
        __threadfence();
    }
    __syncthreads();
}

// ---------------- single persistent kernel ----------------
__global__ __launch_bounds__(TPB, 1)
void k_fused(const float* __restrict__ feats,
             const float* __restrict__ memory,
             const int*   __restrict__ seg,
             float*       __restrict__ out) {
    __shared__ float tile[32][33];
    __shared__ __align__(16) float fsm[32 * CH];     // 32 taps * 64 ch   (8 KB)
    __shared__ __align__(16) float csm[32 * CPAD];   // 32 taps * 128 cls (16 KB)
    __shared__ float s_den[CPAD], s_cnt[CPAD];
    __shared__ int   s_isz[CPAD];

    const int tid = threadIdx.x;
    const int bid = blockIdx.x;

    // ================= P0: transpose + zero =================
    {
        const int tx = tid & 31, ty = tid >> 5;        // ty 0..15
        for (int st = bid; st < 900; st += GRID) {
            const int spT = (st % 450) * 32;
            const int chT = (st / 450) * 32;
#pragma unroll
            for (int k = 0; k < 32; k += 16)
                tile[ty + k][tx] = feats[(chT + ty + k) * NTAP + spT + tx];
            __syncthreads();
#pragma unroll
            for (int k = 0; k < 32; k += 16)
                g_featsT[(spT + ty + k) * CH + chT + tx] = tile[tx][ty + k];
            __syncthreads();
        }
        const float4 z = make_float4(0.f, 0.f, 0.f, 0.f);
        for (int i = bid * TPB + tid; i < NTAP * CPAD / 4; i += STRIDE)
            ((float4*)g_C)[i] = z;
        const int gi = bid * TPB + tid;
        if (gi < NC * CH) g_acc[gi] = 0.f;
        if (gi < CPAD) { g_den[gi] = 0.f; g_cnt[gi] = 0.f; }
        if (bid == 0 && tid < NC) {
            int isz = 1;
#pragma unroll
            for (int k = 0; k < 16; k++) {
                float4 v = ((const float4*)memory)[tid * 16 + k];
                isz &= (v.x == 0.f) & (v.y == 0.f) & (v.z == 0.f) & (v.w == 0.f);
            }
            g_iszero[tid] = isz;
        }
    }
    grid_barrier(0);

    // ================= P1a: neighbor Gram (warp per tap) =================
    {
        const int w = tid >> 5, lane = tid & 31;
        for (int t = bid * 16 + w; t < NTAP; t += GRID * 16) {
            const int y = t / IN_HW, x = t - y * IN_HW;
            const int xp = min(x + 1, IN_HW - 1), yp = min(y + 1, IN_HW - 1);
            const float2 a = *(const float2*)&g_featsT[(y  * IN_HW + x ) * CH + lane * 2];
            const float2 b = *(const float2*)&g_featsT[(y  * IN_HW + xp) * CH + lane * 2];
            const float2 c = *(const float2*)&g_featsT[(yp * IN_HW + x ) * CH + lane * 2];
            const float2 d = *(const float2*)&g_featsT[(yp * IN_HW + xp) * CH + lane * 2];
            float s  = a.x * a.x + a.y * a.y;
            float h  = a.x * b.x + a.y * b.y;
            float vv = a.x * c.x + a.y * c.y;
            float dd = a.x * d.x + a.y * d.y;
            float ad = b.x * c.x + b.y * c.y;
#pragma unroll
            for (int m = 16; m; m >>= 1) {
                s  += __shfl_xor_sync(0xffffffffu, s,  m);
                h  += __shfl_xor_sync(0xffffffffu, h,  m);
                vv += __shfl_xor_sync(0xffffffffu, vv, m);
                dd += __shfl_xor_sync(0xffffffffu, dd, m);
                ad += __shfl_xor_sync(0xffffffffu, ad, m);
            }
            if (lane == 0) {
                float* o = &g_gram[t * 8];
                o[0] = s; o[1] = h; o[2] = vv; o[3] = dd; o[4] = ad;
            }
        }
    }
    __syncthreads();

    // ================= P1b: G table  G[t][c] = f_t . mn_c =================
    {
        const int c = tid >> 2, q = tid & 3;            // c 0..127, q 0..3
        const bool valid = c < NC;
        float4 mq[4];
        float n2p = 0.f;
#pragma unroll
        for (int j = 0; j < 4; j++) {
            float4 v = valid ? ((const float4*)memory)[c * 16 + q * 4 + j]
                             : make_float4(0.f, 0.f, 0.f, 0.f);
            n2p += v.x * v.x + v.y * v.y + v.z * v.z + v.w * v.w;
            mq[j] = v;
        }
        n2p += __shfl_xor_sync(0xffffffffu, n2p, 1);
        n2p += __shfl_xor_sync(0xffffffffu, n2p, 2);
        const float inv = 1.0f / fmaxf(sqrtf(n2p), EPSV);
#pragma unroll
        for (int j = 0; j < 4; j++) {
            mq[j].x *= inv; mq[j].y *= inv; mq[j].z *= inv; mq[j].w *= inv;
        }
        for (int grp = bid; grp < 450; grp += GRID) {   // 32 taps per group
            const int t0 = grp * 32;
            __syncthreads();
            ((float4*)fsm)[tid] = ((const float4*)(g_featsT + t0 * CH))[tid];
            __syncthreads();
#pragma unroll 4
            for (int tt = 0; tt < 32; tt++) {
                const float4* fr = (const float4*)(fsm + tt * CH + q * 16);
                float a0 = 0.f, a1 = 0.f, a2 = 0.f, a3 = 0.f;
#pragma unroll
                for (int j = 0; j < 4; j++) {
                    float4 f = fr[j];
                    a0 = fmaf(f.x, mq[j].x, a0);
                    a1 = fmaf(f.y, mq[j].y, a1);
                    a2 = fmaf(f.z, mq[j].z, a2);
                    a3 = fmaf(f.w, mq[j].w, a3);
                }
                float d = (a0 + a1) + (a2 + a3);
                d += __shfl_xor_sync(0xffffffffu, d, 1);
                d += __shfl_xor_sync(0xffffffffu, d, 2);
                if (q == 0 && valid) g_G[(t0 + tt) * CPAD + c] = d;
            }
        }
    }
    grid_barrier(1);

    // ================= P2: per-pixel weights + coefficient scatter =================
    {
        if (tid < CPAD) {
            s_den[tid] = 0.f; s_cnt[tid] = 0.f;
            s_isz[tid] = (tid < NC) ? g_iszero[tid] : 0;
        }
        __syncthreads();
        for (int i = bid * TPB + tid; i < NPIX; i += STRIDE) {
            const int oy = i / OUT_HW, ox = i - oy * OUT_HW;
            const int c = seg[i];
            const float fy = 0.25f * (float)oy - 0.375f;
            const float fx = 0.25f * (float)ox - 0.375f;
            const int by = (int)floorf(fy), bx = (int)floorf(fx);
            int y0, x0; float u, v;
            if (by < 0)               { y0 = 0;         u = 0.f; }
            else if (by >= IN_HW - 1) { y0 = IN_HW - 1; u = 0.f; }
            else                      { y0 = by;        u = fy - (float)by; }
            if (bx < 0)               { x0 = 0;         v = 0.f; }
            else if (bx >= IN_HW - 1) { x0 = IN_HW - 1; v = 0.f; }
            else                      { x0 = bx;        v = fx - (float)bx; }
            const int yp = min(y0 + 1, IN_HW - 1), xp = min(x0 + 1, IN_HW - 1);
            const float wu0 = 1.f - u, wv0 = 1.f - v;
            const float w00 = wu0 * wv0, w01 = wu0 * v, w10 = u * wv0, w11 = u * v;
            const int t00 = y0 * IN_HW + x0, t01 = y0 * IN_HW + xp;
            const int t10 = yp * IN_HW + x0, t11 = yp * IN_HW + xp;

            const float dot = w00 * g_G[t00 * CPAD + c] + w01 * g_G[t01 * CPAD + c]
                            + w10 * g_G[t10 * CPAD + c] + w11 * g_G[t11 * CPAD + c];

            const float4 q00 = *(const float4*)&g_gram[t00 * 8];
            const float ad00 = g_gram[t00 * 8 + 4];
            const float4 q01 = *(const float4*)&g_gram[t01 * 8];
            const float4 q10 = *(const float4*)&g_gram[t10 * 8];
            const float S11  = g_gram[t11 * 8];

            float n2 = w00 * w00 * q00.x + w01 * w01 * q01.x + w10 * w10 * q10.x
                     + w11 * w11 * S11
                     + 2.f * (w00 * w01 * q00.y + w10 * w11 * q10.y
                            + w00 * w10 * q00.z + w01 * w11 * q01.z
                            + w00 * w11 * q00.w + w01 * w10 * ad00);
            n2 = fmaxf(n2, 0.f);
            const float s = 1.f - dot / fmaxf(sqrtf(n2), EPSV);

            const float cm = s_isz[c] ? 1.0f : s;
            atomicAdd(&g_C[t00 * CPAD + c], cm * w00);
            atomicAdd(&g_C[t01 * CPAD + c], cm * w01);
            atomicAdd(&g_C[t10 * CPAD + c], cm * w10);
            atomicAdd(&g_C[t11 * CPAD + c], cm * w11);
            atomicAdd(&s_den[c], cm);
            atomicAdd(&s_cnt[c], 1.0f);
        }
        __syncthreads();
        if (tid < NC) {
            atomicAdd(&g_den[tid], s_den[tid]);
            atomicAdd(&g_cnt[tid], s_cnt[tid]);
        }
    }
    grid_barrier(2);

    // ================= P3: output GEMM  acc[c][ch] += sum_t C[t][c] f[t][ch] =========
    {
        const int c = tid >> 2, q = tid & 3;
        const bool valid = c < NC;
        float4 acc[4];
#pragma unroll
        for (int j = 0; j < 4; j++) acc[j] = make_float4(0.f, 0.f, 0.f, 0.f);

        for (int grp = bid; grp < 450; grp += GRID) {
            const int t0 = grp * 32;
            __syncthreads();
            ((float4*)fsm)[tid] = ((const float4*)(g_featsT + t0 * CH))[tid];
            ((float4*)csm)[tid * 2]     = ((const float4*)(g_C + t0 * CPAD))[tid * 2];
            ((float4*)csm)[tid * 2 + 1] = ((const float4*)(g_C + t0 * CPAD))[tid * 2 + 1];
            __syncthreads();
#pragma unroll 4
            for (int tt = 0; tt < 32; tt++) {
                const float coef = csm[tt * CPAD + c];
                const float4* fr = (const float4*)(fsm + tt * CH + q * 16);
#pragma unroll
                for (int j = 0; j < 4; j++) {
                    float4 f = fr[j];
                    acc[j].x = fmaf(coef, f.x, acc[j].x);
                    acc[j].y = fmaf(coef, f.y, acc[j].y);
                    acc[j].z = fmaf(coef, f.z, acc[j].z);
                    acc[j].w = fmaf(coef, f.w, acc[j].w);
                }
            }
        }
        if (valid) {
            float* dst = &g_acc[c * CH + q * 16];
#pragma unroll
            for (int j = 0; j < 4; j++) {
                atomicAdd(dst + j * 4 + 0, acc[j].x);
                atomicAdd(dst + j * 4 + 1, acc[j].y);
                atomicAdd(dst + j * 4 + 2, acc[j].z);
                atomicAdd(dst + j * 4 + 3, acc[j].w);
            }
        }
    }
    grid_barrier(3);

    // ================= P4: final blend (block 0) =================
    if (bid == 0) {
        for (int idx = tid; idx < NC * CH; idx += TPB) {
            const int c = idx >> 6, ch = idx & 63;
            const float mem = memory[c * CH + ch];
            const float cnt = g_cnt[c];
            float o;
            if (cnt < 0.5f) {
                o = mem;
            } else if (g_iszero[c]) {
                o = g_acc[c * CH + ch] / fmaxf(g_den[c], 1.0f);
            } else {
                const float dv = g_den[c];
                const float denom = (dv != 0.0f) ? dv : 1.0f;
                o = 0.9f * mem + 0.1f * (g_acc[c * CH + ch] / denom);
            }
            out[c * CH + ch] = o;
        }
    }
}

// ---------------- launch ----------------
extern "C" void kernel_launch(void* const* d_in, const int* in_sizes, int n_in,
                              void* d_out, int out_size) {
    const float* feats  = (const float*)d_in[0];   // (1,64,120,120)
    const float* memory = (const float*)d_in[1];   // (124,1,64)
    const int*   seg    = (const int*)d_in[2];     // (1,480,480)
    float* out = (float*)d_out;                    // (124,1,64)

    k_fused<<<GRID, TPB>>>(feats, memory, seg, out);
}

// round 10
// speedup vs baseline: 1.2268x; 1.2268x over previous
#include <cuda_runtime.h>
#include <math.h>

#define NC     124
#define CPAD   128
#define CH     64
#define IN_HW  120
#define OUT_HW 480
#define NPIX   (OUT_HW * OUT_HW)   // 230400
#define NTAP   (IN_HW * IN_HW)     // 14400
#define EPSV   1e-8f

// ---------------- static device scratch ----------------
__device__ __align__(16) float g_featsT[NTAP * CH];   // (tap, ch)
__device__ int   g_iszero[NC];
__device__ __align__(16) float g_gram[NTAP * 8];      // S,H,V,D,AD per tap
__device__ __align__(16) float g_G[NTAP * CPAD];      // f_t . mn_c
__device__ __align__(16) float g_C[NTAP * CPAD];      // selected coefficient
__device__ float g_acc[NC * CH];
__device__ float g_den[CPAD];
__device__ float g_cnt[CPAD];
__device__ int   g_done;                               // k_out completion counter

// ---------------- K1: transpose feats + zero accumulators ----------------
__global__ __launch_bounds__(256) void k_init(const float* __restrict__ feats) {
    __shared__ float tile[32][33];
    const int bid = blockIdx.x;                 // 0..899
    const int tid = threadIdx.x;
    const int tx = tid & 31, ty = tid >> 5;
    const int spT = (bid % 450) * 32;
    const int chT = (bid / 450) * 32;

#pragma unroll
    for (int k = 0; k < 32; k += 8)
        tile[ty + k][tx] = feats[(chT + ty + k) * NTAP + spT + tx];
    __syncthreads();
#pragma unroll
    for (int k = 0; k < 32; k += 8)
        g_featsT[(spT + ty + k) * CH + chT + tx] = tile[tx][ty + k];

    const int gid = bid * 256 + tid;            // 230400 threads * 8 floats = NTAP*CPAD
    const float4 z = make_float4(0.f, 0.f, 0.f, 0.f);
    ((float4*)g_C)[gid * 2]     = z;
    ((float4*)g_C)[gid * 2 + 1] = z;
    if (gid < NC * CH) g_acc[gid] = 0.f;
    if (gid < CPAD) { g_den[gid] = 0.f; g_cnt[gid] = 0.f; }
}

// ---------------- K2: gram (blocks 0..899) + G table (blocks 900..1499) -------
__global__ __launch_bounds__(512) void k_gramG(const float* __restrict__ memory) {
    if (blockIdx.x < 900) {
        // ---- neighbor Gram: warp per tap, 16 taps per block ----
        const int w = threadIdx.x >> 5, lane = threadIdx.x & 31;
        const int t = blockIdx.x * 16 + w;
        const int y = t / IN_HW, x = t - y * IN_HW;
        const int xp = min(x + 1, IN_HW - 1), yp = min(y + 1, IN_HW - 1);
        const float2 a = *(const float2*)&g_featsT[(y  * IN_HW + x ) * CH + lane * 2];
        const float2 b = *(const float2*)&g_featsT[(y  * IN_HW + xp) * CH + lane * 2];
        const float2 c = *(const float2*)&g_featsT[(yp * IN_HW + x ) * CH + lane * 2];
        const float2 d = *(const float2*)&g_featsT[(yp * IN_HW + xp) * CH + lane * 2];
        float s  = a.x * a.x + a.y * a.y;
        float h  = a.x * b.x + a.y * b.y;
        float vv = a.x * c.x + a.y * c.y;
        float dd = a.x * d.x + a.y * d.y;
        float ad = b.x * c.x + b.y * c.y;
#pragma unroll
        for (int m = 16; m; m >>= 1) {
            s  += __shfl_xor_sync(0xffffffffu, s,  m);
            h  += __shfl_xor_sync(0xffffffffu, h,  m);
            vv += __shfl_xor_sync(0xffffffffu, vv, m);
            dd += __shfl_xor_sync(0xffffffffu, dd, m);
            ad += __shfl_xor_sync(0xffffffffu, ad, m);
        }
        if (lane == 0) {
            float* o = &g_gram[t * 8];
            o[0] = s; o[1] = h; o[2] = vv; o[3] = dd; o[4] = ad;
        }
        if (blockIdx.x == 0 && threadIdx.x < NC) {
            int isz = 1;
#pragma unroll
            for (int k = 0; k < 16; k++) {
                float4 v = ((const float4*)memory)[threadIdx.x * 16 + k];
                isz &= (v.x == 0.f) & (v.y == 0.f) & (v.z == 0.f) & (v.w == 0.f);
            }
            g_iszero[threadIdx.x] = isz;
        }
    } else {
        // ---- G table: (c,q) layout, 24 taps per block, 600 blocks ----
        __shared__ __align__(16) float fsm[24 * CH];      // 6 KB
        const int tid = threadIdx.x;
        const int c = tid >> 2, q = tid & 3;
        const bool valid = c < NC;
        float4 mq[4];
        float n2p = 0.f;
#pragma unroll
        for (int j = 0; j < 4; j++) {
            float4 v = valid ? ((const float4*)memory)[c * 16 + q * 4 + j]
                             : make_float4(0.f, 0.f, 0.f, 0.f);
            n2p += v.x * v.x + v.y * v.y + v.z * v.z + v.w * v.w;
            mq[j] = v;
        }
        n2p += __shfl_xor_sync(0xffffffffu, n2p, 1);
        n2p += __shfl_xor_sync(0xffffffffu, n2p, 2);
        const float inv = 1.0f / fmaxf(sqrtf(n2p), EPSV);
#pragma unroll
        for (int j = 0; j < 4; j++) {
            mq[j].x *= inv; mq[j].y *= inv; mq[j].z *= inv; mq[j].w *= inv;
        }
        const int t0 = (blockIdx.x - 900) * 24;
        if (tid < 384)
            ((float4*)fsm)[tid] = ((const float4*)(g_featsT + t0 * CH))[tid];
        __syncthreads();
#pragma unroll 4
        for (int tt = 0; tt < 24; tt++) {
            const float4* fr = (const float4*)(fsm + tt * CH + q * 16);
            float a0 = 0.f, a1 = 0.f, a2 = 0.f, a3 = 0.f;
#pragma unroll
            for (int j = 0; j < 4; j++) {
                float4 f = fr[j];
                a0 = fmaf(f.x, mq[j].x, a0);
                a1 = fmaf(f.y, mq[j].y, a1);
                a2 = fmaf(f.z, mq[j].z, a2);
                a3 = fmaf(f.w, mq[j].w, a3);
            }
            float d = (a0 + a1) + (a2 + a3);
            d += __shfl_xor_sync(0xffffffffu, d, 1);
            d += __shfl_xor_sync(0xffffffffu, d, 2);
            if (q == 0 && valid) g_G[(t0 + tt) * CPAD + c] = d;
        }
    }
}

// ---------------- per-pixel geometry helper ----------------
struct Geo { int t00, t01, t10, t11; float w00, w01, w10, w11; };
__device__ __forceinline__ Geo pix_geo(int i) {
    const int oy = i / OUT_HW, ox = i - oy * OUT_HW;
    const float fy = 0.25f * (float)oy - 0.375f;
    const float fx = 0.25f * (float)ox - 0.375f;
    const int by = (int)floorf(fy), bx = (int)floorf(fx);
    int y0, x0; float u, v;
    if (by < 0)               { y0 = 0;         u = 0.f; }
    else if (by >= IN_HW - 1) { y0 = IN_HW - 1; u = 0.f; }
    else                      { y0 = by;        u = fy - (float)by; }
    if (bx < 0)               { x0 = 0;         v = 0.f; }
    else if (bx >= IN_HW - 1) { x0 = IN_HW - 1; v = 0.f; }
    else                      { x0 = bx;        v = fx - (float)bx; }
    const int yp = min(y0 + 1, IN_HW - 1), xp = min(x0 + 1, IN_HW - 1);
    const float wu0 = 1.f - u, wv0 = 1.f - v;
    Geo g;
    g.w00 = wu0 * wv0; g.w01 = wu0 * v; g.w10 = u * wv0; g.w11 = u * v;
    g.t00 = y0 * IN_HW + x0; g.t01 = y0 * IN_HW + xp;
    g.t10 = yp * IN_HW + x0; g.t11 = yp * IN_HW + xp;
    return g;
}

__device__ __forceinline__ float pix_sim(const Geo& g, int c) {
    const float dot = g.w00 * g_G[g.t00 * CPAD + c] + g.w01 * g_G[g.t01 * CPAD + c]
                    + g.w10 * g_G[g.t10 * CPAD + c] + g.w11 * g_G[g.t11 * CPAD + c];
    const float4 q00 = *(const float4*)&g_gram[g.t00 * 8];
    const float ad00 = g_gram[g.t00 * 8 + 4];
    const float4 q01 = *(const float4*)&g_gram[g.t01 * 8];
    const float4 q10 = *(const float4*)&g_gram[g.t10 * 8];
    const float S11  = g_gram[g.t11 * 8];
    float n2 = g.w00 * g.w00 * q00.x + g.w01 * g.w01 * q01.x
             + g.w10 * g.w10 * q10.x + g.w11 * g.w11 * S11
             + 2.f * (g.w00 * g.w01 * q00.y + g.w10 * g.w11 * q10.y
                    + g.w00 * g.w10 * q00.z + g.w01 * g.w11 * q01.z
                    + g.w00 * g.w11 * q00.w + g.w01 * g.w10 * ad00);
    n2 = fmaxf(n2, 0.f);
    return 1.f - dot / fmaxf(sqrtf(n2), EPSV);
}

// ---------------- K3: per-pixel weights + coefficient scatter (2 px/thread) ---
__global__ __launch_bounds__(512) void k_phaseA(const int* __restrict__ seg) {
    __shared__ float s_den[CPAD], s_cnt[CPAD];
    __shared__ int   s_isz[CPAD];
    const int tid = threadIdx.x;
    if (tid < CPAD) {
        s_den[tid] = 0.f; s_cnt[tid] = 0.f;
        s_isz[tid] = (tid < NC) ? g_iszero[tid] : 0;
    }
    __syncthreads();

    const int iA = blockIdx.x * 512 + tid;        // grid 225: iA < 115200
    const int iB = iA + NPIX / 2;
    const int cA = seg[iA];
    const int cB = seg[iB];
    const Geo ga = pix_geo(iA);
    const Geo gb = pix_geo(iB);

    const float sA = pix_sim(ga, cA);
    const float sB = pix_sim(gb, cB);

    const float cmA = s_isz[cA] ? 1.0f : sA;
    const float cmB = s_isz[cB] ? 1.0f : sB;

    atomicAdd(&g_C[ga.t00 * CPAD + cA], cmA * ga.w00);
    atomicAdd(&g_C[ga.t01 * CPAD + cA], cmA * ga.w01);
    atomicAdd(&g_C[ga.t10 * CPAD + cA], cmA * ga.w10);
    atomicAdd(&g_C[ga.t11 * CPAD + cA], cmA * ga.w11);
    atomicAdd(&g_C[gb.t00 * CPAD + cB], cmB * gb.w00);
    atomicAdd(&g_C[gb.t01 * CPAD + cB], cmB * gb.w01);
    atomicAdd(&g_C[gb.t10 * CPAD + cB], cmB * gb.w10);
    atomicAdd(&g_C[gb.t11 * CPAD + cB], cmB * gb.w11);
    atomicAdd(&s_den[cA], cmA);
    atomicAdd(&s_cnt[cA], 1.0f);
    atomicAdd(&s_den[cB], cmB);
    atomicAdd(&s_cnt[cB], 1.0f);

    __syncthreads();
    if (tid < NC) {
        atomicAdd(&g_den[tid], s_den[tid]);
        atomicAdd(&g_cnt[tid], s_cnt[tid]);
    }
}

// ---------------- K4: output GEMM + fused blend (last-block) -------------------
__global__ __launch_bounds__(512) void k_out(const float* __restrict__ memory,
                                             float* __restrict__ out) {
    __shared__ __align__(16) float fsm[32 * CH];     // 8 KB
    __shared__ __align__(16) float csm[32 * CPAD];   // 16 KB
    __shared__ int amLast;
    const int tid = threadIdx.x;
    const int c = tid >> 2, q = tid & 3;
    const bool valid = c < NC;
    float4 acc[4];
#pragma unroll
    for (int j = 0; j < 4; j++) acc[j] = make_float4(0.f, 0.f, 0.f, 0.f);

    for (int grp = blockIdx.x; grp < 450; grp += 148) {
        const int t0 = grp * 32;
        __syncthreads();
        ((float4*)fsm)[tid] = ((const float4*)(g_featsT + t0 * CH))[tid];
        ((float4*)csm)[tid * 2]     = ((const float4*)(g_C + t0 * CPAD))[tid * 2];
        ((float4*)csm)[tid * 2 + 1] = ((const float4*)(g_C + t0 * CPAD))[tid * 2 + 1];
        __syncthreads();
#pragma unroll 4
        for (int tt = 0; tt < 32; tt++) {
            const float coef = csm[tt * CPAD + c];
            const float4* fr = (const float4*)(fsm + tt * CH + q * 16);
#pragma unroll
            for (int j = 0; j < 4; j++) {
                float4 f = fr[j];
                acc[j].x = fmaf(coef, f.x, acc[j].x);
                acc[j].y = fmaf(coef, f.y, acc[j].y);
                acc[j].z = fmaf(coef, f.z, acc[j].z);
                acc[j].w = fmaf(coef, f.w, acc[j].w);
            }
        }
    }
    if (valid) {
        float* dst = &g_acc[c * CH + q * 16];
#pragma unroll
        for (int j = 0; j < 4; j++) {
            atomicAdd(dst + j * 4 + 0, acc[j].x);
            atomicAdd(dst + j * 4 + 1, acc[j].y);
            atomicAdd(dst + j * 4 + 2, acc[j].z);
            atomicAdd(dst + j * 4 + 3, acc[j].w);
        }
    }

    // last-block fused blend
    __threadfence();
    __syncthreads();
    if (tid == 0) {
        const int prev = atomicAdd(&g_done, 1);
        amLast = (prev == 147);
        if (amLast) g_done = 0;              // reset for next graph replay
    }
    __syncthreads();
    if (amLast) {
        for (int idx = tid; idx < NC * CH; idx += 512) {
            const int cc = idx >> 6, ch = idx & 63;
            const float mem = memory[cc * CH + ch];
            const float cnt = g_cnt[cc];
            float o;
            if (cnt < 0.5f) {
                o = mem;
            } else if (g_iszero[cc]) {
                o = g_acc[cc * CH + ch] / fmaxf(g_den[cc], 1.0f);
            } else {
                const float dv = g_den[cc];
                const float denom = (dv != 0.0f) ? dv : 1.0f;
                o = 0.9f * mem + 0.1f * (g_acc[cc * CH + ch] / denom);
            }
            out[cc * CH + ch] = o;
        }
    }
}

// ---------------- launch ----------------
extern "C" void kernel_launch(void* const* d_in, const int* in_sizes, int n_in,
                              void* d_out, int out_size) {
    const float* feats  = (const float*)d_in[0];   // (1,64,120,120)
    const float* memory = (const float*)d_in[1];   // (124,1,64)
    const int*   seg    = (const int*)d_in[2];     // (1,480,480)
    float* out = (float*)d_out;                    // (124,1,64)

    k_init<<<900, 256>>>(feats);
    k_gramG<<<1500, 512>>>(memory);
    k_phaseA<<<225, 512>>>(seg);
    k_out<<<148, 512>>>(memory, out);
}

// round 13
// speedup vs baseline: 1.9328x; 1.5755x over previous
#include <cuda_runtime.h>
#include <math.h>

#define NC     124
#define CPAD   128
#define CH     64
#define IN_HW  120
#define OUT_HW 480
#define NPIX   (OUT_HW * OUT_HW)   // 230400
#define NTAP   (IN_HW * IN_HW)     // 14400
#define EPSV   1e-8f
#define NOUTB  300                  // k_out blocks (48 taps each)

// ---------------- static device scratch ----------------
__device__ __align__(16) float g_featsT[NTAP * CH];   // (tap, ch)
__device__ int   g_iszero[NC];
__device__ __align__(16) float g_gram[NTAP * 8];      // S,H,V,D,AD per tap
__device__ __align__(16) float g_G[NTAP * CPAD];      // f_t . mn_c
__device__ __align__(16) float g_C[NTAP * CPAD];      // selected coefficient
__device__ __align__(16) float4 g_part4[NOUTB * 2048]; // k_out partials (9.8MB)
__device__ float g_den[CPAD];
__device__ float g_cnt[CPAD];

// ---------------- K1: transpose feats + zero accumulators ----------------
__global__ __launch_bounds__(256) void k_init(const float* __restrict__ feats) {
    __shared__ float tile[32][33];
    const int bid = blockIdx.x;                 // 0..899
    const int tid = threadIdx.x;
    const int tx = tid & 31, ty = tid >> 5;
    const int spT = (bid % 450) * 32;
    const int chT = (bid / 450) * 32;

#pragma unroll
    for (int k = 0; k < 32; k += 8)
        tile[ty + k][tx] = feats[(chT + ty + k) * NTAP + spT + tx];
    __syncthreads();
#pragma unroll
    for (int k = 0; k < 32; k += 8)
        g_featsT[(spT + ty + k) * CH + chT + tx] = tile[tx][ty + k];

    const int gid = bid * 256 + tid;            // 230400 threads * 8 floats = NTAP*CPAD
    const float4 z = make_float4(0.f, 0.f, 0.f, 0.f);
    ((float4*)g_C)[gid * 2]     = z;
    ((float4*)g_C)[gid * 2 + 1] = z;
    if (gid < CPAD) { g_den[gid] = 0.f; g_cnt[gid] = 0.f; }
}

// ---------------- K2: gram (blocks 0..899) + G table (blocks 900..1499) -------
__global__ __launch_bounds__(512) void k_gramG(const float* __restrict__ memory) {
    if (blockIdx.x < 900) {
        // ---- neighbor Gram: warp per tap, 16 taps per block ----
        const int w = threadIdx.x >> 5, lane = threadIdx.x & 31;
        const int t = blockIdx.x * 16 + w;
        const int y = t / IN_HW, x = t - y * IN_HW;
        const int xp = min(x + 1, IN_HW - 1), yp = min(y + 1, IN_HW - 1);
        const float2 a = *(const float2*)&g_featsT[(y  * IN_HW + x ) * CH + lane * 2];
        const float2 b = *(const float2*)&g_featsT[(y  * IN_HW + xp) * CH + lane * 2];
        const float2 c = *(const float2*)&g_featsT[(yp * IN_HW + x ) * CH + lane * 2];
        const float2 d = *(const float2*)&g_featsT[(yp * IN_HW + xp) * CH + lane * 2];
        float s  = a.x * a.x + a.y * a.y;
        float h  = a.x * b.x + a.y * b.y;
        float vv = a.x * c.x + a.y * c.y;
        float dd = a.x * d.x + a.y * d.y;
        float ad = b.x * c.x + b.y * c.y;
#pragma unroll
        for (int m = 16; m; m >>= 1) {
            s  += __shfl_xor_sync(0xffffffffu, s,  m);
            h  += __shfl_xor_sync(0xffffffffu, h,  m);
            vv += __shfl_xor_sync(0xffffffffu, vv, m);
            dd += __shfl_xor_sync(0xffffffffu, dd, m);
            ad += __shfl_xor_sync(0xffffffffu, ad, m);
        }
        if (lane == 0) {
            float* o = &g_gram[t * 8];
            o[0] = s; o[1] = h; o[2] = vv; o[3] = dd; o[4] = ad;
        }
        if (blockIdx.x == 0 && threadIdx.x < NC) {
            int isz = 1;
#pragma unroll
            for (int k = 0; k < 16; k++) {
                float4 v = ((const float4*)memory)[threadIdx.x * 16 + k];
                isz &= (v.x == 0.f) & (v.y == 0.f) & (v.z == 0.f) & (v.w == 0.f);
            }
            g_iszero[threadIdx.x] = isz;
        }
    } else {
        // ---- G table: (c,q) layout, 24 taps per block, 600 blocks ----
        __shared__ __align__(16) float fsm[24 * CH];      // 6 KB
        const int tid = threadIdx.x;
        const int c = tid >> 2, q = tid & 3;
        const bool valid = c < NC;
        float4 mq[4];
        float n2p = 0.f;
#pragma unroll
        for (int j = 0; j < 4; j++) {
            float4 v = valid ? ((const float4*)memory)[c * 16 + q * 4 + j]
                             : make_float4(0.f, 0.f, 0.f, 0.f);
            n2p += v.x * v.x + v.y * v.y + v.z * v.z + v.w * v.w;
            mq[j] = v;
        }
        n2p += __shfl_xor_sync(0xffffffffu, n2p, 1);
        n2p += __shfl_xor_sync(0xffffffffu, n2p, 2);
        const float inv = 1.0f / fmaxf(sqrtf(n2p), EPSV);
#pragma unroll
        for (int j = 0; j < 4; j++) {
            mq[j].x *= inv; mq[j].y *= inv; mq[j].z *= inv; mq[j].w *= inv;
        }
        const int t0 = (blockIdx.x - 900) * 24;
        if (tid < 384)
            ((float4*)fsm)[tid] = ((const float4*)(g_featsT + t0 * CH))[tid];
        __syncthreads();
#pragma unroll 4
        for (int tt = 0; tt < 24; tt++) {
            const float4* fr = (const float4*)(fsm + tt * CH + q * 16);
            float a0 = 0.f, a1 = 0.f, a2 = 0.f, a3 = 0.f;
#pragma unroll
            for (int j = 0; j < 4; j++) {
                float4 f = fr[j];
                a0 = fmaf(f.x, mq[j].x, a0);
                a1 = fmaf(f.y, mq[j].y, a1);
                a2 = fmaf(f.z, mq[j].z, a2);
                a3 = fmaf(f.w, mq[j].w, a3);
            }
            float d = (a0 + a1) + (a2 + a3);
            d += __shfl_xor_sync(0xffffffffu, d, 1);
            d += __shfl_xor_sync(0xffffffffu, d, 2);
            if (q == 0 && valid) g_G[(t0 + tt) * CPAD + c] = d;
        }
    }
}

// ---------------- per-pixel geometry helper ----------------
struct Geo { int t00, t01, t10, t11; float w00, w01, w10, w11; };
__device__ __forceinline__ Geo pix_geo(int i) {
    const int oy = i / OUT_HW, ox = i - oy * OUT_HW;
    const float fy = 0.25f * (float)oy - 0.375f;
    const float fx = 0.25f * (float)ox - 0.375f;
    const int by = (int)floorf(fy), bx = (int)floorf(fx);
    int y0, x0; float u, v;
    if (by < 0)               { y0 = 0;         u = 0.f; }
    else if (by >= IN_HW - 1) { y0 = IN_HW - 1; u = 0.f; }
    else                      { y0 = by;        u = fy - (float)by; }
    if (bx < 0)               { x0 = 0;         v = 0.f; }
    else if (bx >= IN_HW - 1) { x0 = IN_HW - 1; v = 0.f; }
    else                      { x0 = bx;        v = fx - (float)bx; }
    const int yp = min(y0 + 1, IN_HW - 1), xp = min(x0 + 1, IN_HW - 1);
    const float wu0 = 1.f - u, wv0 = 1.f - v;
    Geo g;
    g.w00 = wu0 * wv0; g.w01 = wu0 * v; g.w10 = u * wv0; g.w11 = u * v;
    g.t00 = y0 * IN_HW + x0; g.t01 = y0 * IN_HW + xp;
    g.t10 = yp * IN_HW + x0; g.t11 = yp * IN_HW + xp;
    return g;
}

__device__ __forceinline__ float pix_sim(const Geo& g, int c) {
    const float dot = g.w00 * g_G[g.t00 * CPAD + c] + g.w01 * g_G[g.t01 * CPAD + c]
                    + g.w10 * g_G[g.t10 * CPAD + c] + g.w11 * g_G[g.t11 * CPAD + c];
    const float4 q00 = *(const float4*)&g_gram[g.t00 * 8];
    const float ad00 = g_gram[g.t00 * 8 + 4];
    const float4 q01 = *(const float4*)&g_gram[g.t01 * 8];
    const float4 q10 = *(const float4*)&g_gram[g.t10 * 8];
    const float S11  = g_gram[g.t11 * 8];
    float n2 = g.w00 * g.w00 * q00.x + g.w01 * g.w01 * q01.x
             + g.w10 * g.w10 * q10.x + g.w11 * g.w11 * S11
             + 2.f * (g.w00 * g.w01 * q00.y + g.w10 * g.w11 * q10.y
                    + g.w00 * g.w10 * q00.z + g.w01 * g.w11 * q01.z
                    + g.w00 * g.w11 * q00.w + g.w01 * g.w10 * ad00);
    n2 = fmaxf(n2, 0.f);
    return 1.f - dot / fmaxf(sqrtf(n2), EPSV);
}

// ---------------- K3: per-pixel weights + coefficient scatter (2 px/thread) ---
__global__ __launch_bounds__(512) void k_phaseA(const int* __restrict__ seg) {
    __shared__ float s_den[CPAD], s_cnt[CPAD];
    __shared__ int   s_isz[CPAD];
    const int tid = threadIdx.x;
    if (tid < CPAD) {
        s_den[tid] = 0.f; s_cnt[tid] = 0.f;
        s_isz[tid] = (tid < NC) ? g_iszero[tid] : 0;
    }
    __syncthreads();

    const int iA = blockIdx.x * 512 + tid;        // grid 225: iA < 115200
    const int iB = iA + NPIX / 2;
    const int cA = seg[iA];
    const int cB = seg[iB];
    const Geo ga = pix_geo(iA);
    const Geo gb = pix_geo(iB);

    const float sA = pix_sim(ga, cA);
    const float sB = pix_sim(gb, cB);

    const float cmA = s_isz[cA] ? 1.0f : sA;
    const float cmB = s_isz[cB] ? 1.0f : sB;

    atomicAdd(&g_C[ga.t00 * CPAD + cA], cmA * ga.w00);
    atomicAdd(&g_C[ga.t01 * CPAD + cA], cmA * ga.w01);
    atomicAdd(&g_C[ga.t10 * CPAD + cA], cmA * ga.w10);
    atomicAdd(&g_C[ga.t11 * CPAD + cA], cmA * ga.w11);
    atomicAdd(&g_C[gb.t00 * CPAD + cB], cmB * gb.w00);
    atomicAdd(&g_C[gb.t01 * CPAD + cB], cmB * gb.w01);
    atomicAdd(&g_C[gb.t10 * CPAD + cB], cmB * gb.w10);
    atomicAdd(&g_C[gb.t11 * CPAD + cB], cmB * gb.w11);
    atomicAdd(&s_den[cA], cmA);
    atomicAdd(&s_cnt[cA], 1.0f);
    atomicAdd(&s_den[cB], cmB);
    atomicAdd(&s_cnt[cB], 1.0f);

    __syncthreads();
    if (tid < NC) {
        atomicAdd(&g_den[tid], s_den[tid]);
        atomicAdd(&g_cnt[tid], s_cnt[tid]);
    }
}

// ---------------- K4: output GEMM partials (no atomics, no fence) -------------
// thread (c = tid>>1, h = tid&1); h-interleaved float4 channels:
//   acc[j] covers channels 8j+4h .. 8j+4h+3   (warp reads 2 consecutive f4s)
__global__ __launch_bounds__(256) void k_out() {
    __shared__ __align__(16) float fsm[48 * CH];     // 12 KB
    __shared__ __align__(16) float csm[48 * CPAD];   // 24 KB
    const int tid = threadIdx.x;
    const int c = tid >> 1, h = tid & 1;
    const int t0 = blockIdx.x * 48;                  // 300 * 48 = 14400

#pragma unroll
    for (int k = 0; k < 3; k++)
        ((float4*)fsm)[tid + k * 256] = ((const float4*)(g_featsT + t0 * CH))[tid + k * 256];
#pragma unroll
    for (int k = 0; k < 6; k++)
        ((float4*)csm)[tid + k * 256] = ((const float4*)(g_C + t0 * CPAD))[tid + k * 256];
    __syncthreads();

    float4 acc[8];
#pragma unroll
    for (int j = 0; j < 8; j++) acc[j] = make_float4(0.f, 0.f, 0.f, 0.f);

#pragma unroll 4
    for (int tt = 0; tt < 48; tt++) {
        const float coef = csm[tt * CPAD + c];
        const float4* fr = (const float4*)fsm + tt * 16 + h;
#pragma unroll
        for (int j = 0; j < 8; j++) {
            const float4 f = fr[2 * j];
            acc[j].x = fmaf(coef, f.x, acc[j].x);
            acc[j].y = fmaf(coef, f.y, acc[j].y);
            acc[j].z = fmaf(coef, f.z, acc[j].z);
            acc[j].w = fmaf(coef, f.w, acc[j].w);
        }
    }
    // coalesced partial store: g_part4[(b*8+j)*256 + tid]
#pragma unroll
    for (int j = 0; j < 8; j++)
        g_part4[(blockIdx.x * 8 + j) * 256 + tid] = acc[j];
}

// ---------------- K5: reduce partials + final blend ----------------
__global__ __launch_bounds__(256) void k_blend(const float* __restrict__ memory,
                                               float* __restrict__ out) {
    __shared__ float red[256];
    const int c  = blockIdx.x;                 // 0..123
    const int ch = threadIdx.x & 63;
    const int w  = threadIdx.x >> 6;           // 0..3 split over partials
    const int j  = ch >> 3, h = (ch >> 2) & 1, k = ch & 3;
    const float* P = (const float*)g_part4;
    const int base = (j * 256 + 2 * c + h) * 4 + k;   // + b*8192

    float sum = 0.f;
#pragma unroll 5
    for (int b = w; b < NOUTB; b += 4)
        sum += P[base + b * 8192];
    red[threadIdx.x] = sum;
    __syncthreads();

    if (w == 0) {
        const float accv = red[ch] + red[ch + 64] + red[ch + 128] + red[ch + 192];
        const float mem = memory[c * CH + ch];
        const float cnt = g_cnt[c];
        float o;
        if (cnt < 0.5f) {
            o = mem;                                     // class absent
        } else if (g_iszero[c]) {
            o = accv / fmaxf(g_den[c], 1.0f);            // class mean (den==cnt)
        } else {
            const float dv = g_den[c];
            const float denom = (dv != 0.0f) ? dv : 1.0f;
            o = 0.9f * mem + 0.1f * (accv / denom);      // momentum update
        }
        out[c * CH + ch] = o;
    }
}

// ---------------- launch ----------------
extern "C" void kernel_launch(void* const* d_in, const int* in_sizes, int n_in,
                              void* d_out, int out_size) {
    const float* feats  = (const float*)d_in[0];   // (1,64,120,120)
    const float* memory = (const float*)d_in[1];   // (124,1,64)
    const int*   seg    = (const int*)d_in[2];     // (1,480,480)
    float* out = (float*)d_out;                    // (124,1,64)

    k_init<<<900, 256>>>(feats);
    k_gramG<<<1500, 512>>>(memory);
    k_phaseA<<<225, 512>>>(seg);
    k_out<<<NOUTB, 256>>>();
    k_blend<<<NC, 256>>>(memory, out);
}